// round 5
// baseline (speedup 1.0000x reference)
#include <cuda_runtime.h>
#include <cstdint>

#define D_MODEL 1024
#define HIDDEN  64
#define BATCH   8
#define SEQ     4096
#define ROWS    128     // M-tile per block
#define KC      32      // K chunk for 1024-K GEMMs
#define XSTRIDE 36      // 32 + 4 pad words (rows land 4 banks apart; 144B row = 16B-aligned)
#define YSTRIDE 68      // 64 + 4 pad words (272B row = 16B-aligned)

// Scratch (allocation-free rule: device globals)
__device__ float g_part[256 * HIDDEN * 2];   // per-block partials: (se, swv) per col
__device__ float g_w[BATCH * HIDDEN];

__device__ __forceinline__ uint32_t f2tf(float x) {
    uint32_t r;
    asm("cvt.rna.tf32.f32 %0, %1;" : "=r"(r) : "f"(x));
    return r;
}

__device__ __forceinline__ uint32_t smem_u32(const void* p) {
    return (uint32_t)__cvta_generic_to_shared(p);
}

__device__ __forceinline__ void ldsm_x4(uint32_t r[4], uint32_t addr) {
    asm volatile("ldmatrix.sync.aligned.m8n8.x4.shared.b16 {%0,%1,%2,%3}, [%4];"
                 : "=r"(r[0]), "=r"(r[1]), "=r"(r[2]), "=r"(r[3]) : "r"(addr));
}

__device__ __forceinline__ void mma8(float c[4], const uint32_t a[4], const uint32_t b[2]) {
    asm volatile(
        "mma.sync.aligned.m16n8k8.row.col.f32.tf32.tf32.f32 "
        "{%0,%1,%2,%3}, {%4,%5,%6,%7}, {%8,%9}, {%0,%1,%2,%3};\n"
        : "+f"(c[0]), "+f"(c[1]), "+f"(c[2]), "+f"(c[3])
        : "r"(a[0]), "r"(a[1]), "r"(a[2]), "r"(a[3]), "r"(b[0]), "r"(b[1]));
}

// Compute acc[8][4] += Xtile[128 x 8*KSTEPS] @ Wtile[64 x 8*KSTEPS]^T using ldmatrix frags.
// A: one LDSM.x4 per k8-step (matrices: rows0-7/k0-3, rows8-15/k0-3, rows0-7/k4-7, rows8-15/k4-7).
// B: one LDSM.x4 per k8-step per n16-pair p (matrices: b0/b1 of nt=2p, b0/b1 of nt=2p+1).
template<int STRIDE, int KSTEPS>
__device__ __forceinline__ void mma_tile(uint32_t xs, uint32_t ws, float acc[8][4]) {
    const int lane = threadIdx.x & 31;
    const int warp = threadIdx.x >> 5;
    const uint32_t a_addr = xs +
        ((uint32_t)((warp * 16 + (lane & 7) + ((lane >> 3) & 1) * 8) * STRIDE
                    + ((lane >> 4) & 1) * 4)) * 4u;
    const uint32_t b_addr = ws +
        ((uint32_t)(((lane & 7) + ((lane >> 4) & 1) * 8) * STRIDE
                    + ((lane >> 3) & 1) * 4)) * 4u;
#pragma unroll
    for (int ks = 0; ks < KSTEPS; ks++) {
        uint32_t a[4];
        ldsm_x4(a, a_addr + ks * 32);
#pragma unroll
        for (int p = 0; p < 4; p++) {
            uint32_t b[4];
            ldsm_x4(b, b_addr + (uint32_t)(p * 16 * STRIDE * 4) + ks * 32);
            mma8(acc[2 * p],     a, b);
            mma8(acc[2 * p + 1], a, b + 2);
        }
    }
}

// Stage X[128x32] and W[64x32] chunks (tf32, STS.128)
__device__ __forceinline__ void stage_tiles(const float* __restrict__ X,
                                            const float* __restrict__ W,
                                            int baseRow, int kc,
                                            uint32_t* Xs, uint32_t* Ws) {
    const int tid = threadIdx.x;
    const int r  = tid >> 3;         // 0..31
    const int c4 = (tid & 7) * 4;    // 0,4,...,28
#pragma unroll
    for (int rr = 0; rr < 4; rr++) {
        const float4 v = *(const float4*)(X + (size_t)(baseRow + r + rr * 32) * D_MODEL + kc + c4);
        uint4 o; o.x = f2tf(v.x); o.y = f2tf(v.y); o.z = f2tf(v.z); o.w = f2tf(v.w);
        *(uint4*)(Xs + (r + rr * 32) * XSTRIDE + c4) = o;
    }
#pragma unroll
    for (int rr = 0; rr < 2; rr++) {
        const float4 v = *(const float4*)(W + (size_t)(r + rr * 32) * D_MODEL + kc + c4);
        uint4 o; o.x = f2tf(v.x); o.y = f2tf(v.y); o.z = f2tf(v.z); o.w = f2tf(v.w);
        *(uint4*)(Ws + (r + rr * 32) * XSTRIDE + c4) = o;
    }
}

// P[128x64] = X[baseRow..+128, :1024] @ W[64,1024]^T (no bias)
__device__ __forceinline__ void proj64(const float* __restrict__ X,
                                       const float* __restrict__ W,
                                       int baseRow,
                                       uint32_t* Xs, uint32_t* Ws,
                                       float acc[8][4]) {
    const uint32_t xs = smem_u32(Xs), ws = smem_u32(Ws);
    for (int kc = 0; kc < D_MODEL; kc += KC) {
        stage_tiles(X, W, baseRow, kc, Xs, Ws);
        __syncthreads();
        mma_tile<XSTRIDE, KC / 8>(xs, ws, acc);
        __syncthreads();
    }
}

// ---------------- Kernel 1: fused k&v projections + softmax-pool partials ----------------
// No max-subtraction needed: k = key.Wk + bk has |k| << 80 (sigma ~ 0.58), exp cannot overflow.
__global__ void __launch_bounds__(256) kv_fused_kernel(
    const float* __restrict__ key_in, const float* __restrict__ value_in,
    const float* __restrict__ Wk, const float* __restrict__ bk,
    const float* __restrict__ Wv, const float* __restrict__ bv) {
    __shared__ uint32_t Xs[ROWS * XSTRIDE];
    __shared__ uint32_t Ws[HIDDEN * XSTRIDE];
    __shared__ float pt[8][HIDDEN * 2];   // per-warp (se, swv) per col

    const int tid  = threadIdx.x;
    const int lane = tid & 31;
    const int warp = tid >> 5;
    const int gid  = lane >> 2;
    const int ctid = lane & 3;
    const int baseRow = blockIdx.x * ROWS;

    float accv[8][4] = {};
    proj64(value_in, Wv, baseRow, Xs, Ws, accv);
    float acck[8][4] = {};
    proj64(key_in, Wk, baseRow, Xs, Ws, acck);

    // partials: se[col] = sum_rows exp(k), swv[col] = sum_rows exp(k)*v
#pragma unroll
    for (int nt = 0; nt < 8; nt++) {
        const int col = nt * 8 + 2 * ctid;
        const float bk0 = bk[col], bk1 = bk[col + 1];
        const float bv0 = bv[col], bv1 = bv[col + 1];
        const float e0 = __expf(acck[nt][0] + bk0);
        const float e1 = __expf(acck[nt][1] + bk1);
        const float e2 = __expf(acck[nt][2] + bk0);
        const float e3 = __expf(acck[nt][3] + bk1);
        float se0 = e0 + e2;
        float se1 = e1 + e3;
        float sw0 = e0 * (accv[nt][0] + bv0) + e2 * (accv[nt][2] + bv0);
        float sw1 = e1 * (accv[nt][1] + bv1) + e3 * (accv[nt][3] + bv1);
        // reduce over gid (lanes with same ctid): xor strides 16,8,4
#pragma unroll
        for (int s = 16; s >= 4; s >>= 1) {
            se0 += __shfl_xor_sync(0xffffffffu, se0, s);
            se1 += __shfl_xor_sync(0xffffffffu, se1, s);
            sw0 += __shfl_xor_sync(0xffffffffu, sw0, s);
            sw1 += __shfl_xor_sync(0xffffffffu, sw1, s);
        }
        if (gid == 0) {
            pt[warp][2 * col]           = se0;
            pt[warp][2 * col + 1]       = sw0;
            pt[warp][2 * (col + 1)]     = se1;
            pt[warp][2 * (col + 1) + 1] = sw1;
        }
    }
    __syncthreads();
    if (tid < HIDDEN) {
        float se = 0.f, sw = 0.f;
#pragma unroll
        for (int w = 0; w < 8; w++) {
            se += pt[w][2 * tid];
            sw += pt[w][2 * tid + 1];
        }
        g_part[(blockIdx.x * HIDDEN + tid) * 2]     = se;
        g_part[(blockIdx.x * HIDDEN + tid) * 2 + 1] = sw;
    }
}

// ---------------- Kernel 2: combine per-block partials -> g_w ----------------
__global__ void __launch_bounds__(512) reduce2_kernel() {
    const int tid = threadIdx.x;         // 512 = 8 batches x 64 cols
    const int b = tid >> 6, h = tid & 63;
    float se = 0.f, sw = 0.f;
#pragma unroll 4
    for (int i = 0; i < 32; i++) {
        const int blk = b * 32 + i;      // 32 row-blocks per batch
        se += g_part[(blk * HIDDEN + h) * 2];
        sw += g_part[(blk * HIDDEN + h) * 2 + 1];
    }
    g_w[tid] = sw / se;
}

// ---------------- Kernel 3: fused q-proj -> sigmoid*weights -> Wp proj ----------------
__global__ void __launch_bounds__(256) out_kernel(
    const float* __restrict__ query, const float* __restrict__ Wq,
    const float* __restrict__ bq, const float* __restrict__ Wp,
    const float* __restrict__ bp, float* __restrict__ out) {
    extern __shared__ uint32_t smem[];
    uint32_t* Xs  = smem;                  // stage 1 [128*36]
    uint32_t* Wss = smem + ROWS * XSTRIDE; // stage 1 [64*36]
    uint32_t* Ys  = smem;                  // stage 2 (aliases stage-1 region) [128*68]
    uint32_t* Ps  = smem + ROWS * YSTRIDE; // stage 2 [64*68]

    const int tid  = threadIdx.x;
    const int warp = tid >> 5;
    const int lane = tid & 31;
    const int gid  = lane >> 2;
    const int ctid = lane & 3;
    const int baseRow = blockIdx.x * ROWS;
    const int bidx = baseRow >> 12;        // 4096 rows per batch

    // ---- stage 1: q = query @ Wq^T ----
    float acc[8][4] = {};
    proj64(query, Wq, baseRow, Xs, Wss, acc);

    // epilogue: sigmoid(q + bq) * weights -> Ys (tf32)
#pragma unroll
    for (int nt = 0; nt < 8; nt++) {
        const int col = nt * 8 + 2 * ctid;
        const float b0 = bq[col], b1 = bq[col + 1];
        const float w0 = g_w[bidx * HIDDEN + col], w1 = g_w[bidx * HIDDEN + col + 1];
        const int r = warp * 16 + gid;
        const float q0 = acc[nt][0] + b0, q1 = acc[nt][1] + b1;
        const float q2 = acc[nt][2] + b0, q3 = acc[nt][3] + b1;
        Ys[r * YSTRIDE + col]           = f2tf(w0 / (1.f + __expf(-q0)));
        Ys[r * YSTRIDE + col + 1]       = f2tf(w1 / (1.f + __expf(-q1)));
        Ys[(r + 8) * YSTRIDE + col]     = f2tf(w0 / (1.f + __expf(-q2)));
        Ys[(r + 8) * YSTRIDE + col + 1] = f2tf(w1 / (1.f + __expf(-q3)));
    }

    const uint32_t ys_u = smem_u32(Ys), ps_u = smem_u32(Ps);

    // ---- stage 2: out = Ys @ Wp^T + bp, 16 chunks of 64 output cols ----
    for (int nc = 0; nc < D_MODEL; nc += 64) {
        __syncthreads();   // Ys ready (nc=0) / previous Ps consumers done
        {
            // Stage Wp chunk [64 n-rows x 64 k-cols] -> Ps
            const int r  = tid >> 2;         // 0..63
            const int c4 = (tid & 3) * 4;    // 0,4,8,12
#pragma unroll
            for (int cc = 0; cc < HIDDEN; cc += 16) {
                const float4 v = *(const float4*)(Wp + (size_t)(nc + r) * HIDDEN + cc + c4);
                uint4 o; o.x = f2tf(v.x); o.y = f2tf(v.y); o.z = f2tf(v.z); o.w = f2tf(v.w);
                *(uint4*)(Ps + r * YSTRIDE + cc + c4) = o;
            }
        }
        __syncthreads();

        float oacc[8][4] = {};
        mma_tile<YSTRIDE, HIDDEN / 8>(ys_u, ps_u, oacc);

        // epilogue: + bp, store
#pragma unroll
        for (int nt = 0; nt < 8; nt++) {
            const int col = nc + nt * 8 + 2 * ctid;
            const float b0 = bp[col], b1 = bp[col + 1];
            const size_t r0 = (size_t)(baseRow + warp * 16 + gid);
            *(float2*)(out + r0 * D_MODEL + col) = make_float2(oacc[nt][0] + b0, oacc[nt][1] + b1);
            *(float2*)(out + (r0 + 8) * D_MODEL + col) = make_float2(oacc[nt][2] + b0, oacc[nt][3] + b1);
        }
    }
}

extern "C" void kernel_launch(void* const* d_in, const int* in_sizes, int n_in,
                              void* d_out, int out_size) {
    const float* query = (const float*)d_in[0];
    const float* key_in = (const float*)d_in[1];
    const float* value_in = (const float*)d_in[2];
    const float* Wq = (const float*)d_in[3];
    const float* bq = (const float*)d_in[4];
    const float* Wk = (const float*)d_in[5];
    const float* bk = (const float*)d_in[6];
    const float* Wv = (const float*)d_in[7];
    const float* bv = (const float*)d_in[8];
    const float* Wp = (const float*)d_in[9];
    const float* bp = (const float*)d_in[10];
    float* out = (float*)d_out;

    const int smem3 = (ROWS * YSTRIDE + HIDDEN * YSTRIDE) * 4;  // 52224 B
    cudaFuncSetAttribute(out_kernel, cudaFuncAttributeMaxDynamicSharedMemorySize, smem3);

    kv_fused_kernel<<<256, 256>>>(key_in, value_in, Wk, bk, Wv, bv);
    reduce2_kernel<<<1, 512>>>();
    out_kernel<<<256, 256, smem3>>>(query, Wq, bq, Wp, bp, out);
}

// round 6
// speedup vs baseline: 1.1118x; 1.1118x over previous
#include <cuda_runtime.h>
#include <cstdint>

#define D_MODEL 1024
#define HIDDEN  64
#define BATCH   8
#define SEQ     4096
#define ROWS    128     // M-tile per block
#define KC      32      // K chunk for 1024-K GEMMs
#define XSTRIDE 36      // 32 + 4 pad words (rows land 4 banks apart; 144B row, 16B-aligned)
#define YSTRIDE 68      // 64 + 4 pad words (272B row, 16B-aligned)

#define XBUF_W (ROWS * XSTRIDE)     // 4608 words
#define WBUF_W (HIDDEN * XSTRIDE)   // 2304 words
#define STAGE_W (XBUF_W + WBUF_W)   // 6912 words = 27648 B per stage

// Scratch (allocation-free rule: device globals)
__device__ float g_part[256 * HIDDEN * 2];   // per-block partials: (se, swv) per col
__device__ float g_w[BATCH * HIDDEN];

__device__ __forceinline__ uint32_t f2tf(float x) {
    uint32_t r;
    asm("cvt.rna.tf32.f32 %0, %1;" : "=r"(r) : "f"(x));
    return r;
}

__device__ __forceinline__ uint32_t smem_u32(const void* p) {
    return (uint32_t)__cvta_generic_to_shared(p);
}

__device__ __forceinline__ void ldsm_x4(uint32_t r[4], uint32_t addr) {
    asm volatile("ldmatrix.sync.aligned.m8n8.x4.shared.b16 {%0,%1,%2,%3}, [%4];"
                 : "=r"(r[0]), "=r"(r[1]), "=r"(r[2]), "=r"(r[3]) : "r"(addr));
}

__device__ __forceinline__ void mma8(float c[4], const uint32_t a[4], const uint32_t b[2]) {
    asm volatile(
        "mma.sync.aligned.m16n8k8.row.col.f32.tf32.tf32.f32 "
        "{%0,%1,%2,%3}, {%4,%5,%6,%7}, {%8,%9}, {%0,%1,%2,%3};\n"
        : "+f"(c[0]), "+f"(c[1]), "+f"(c[2]), "+f"(c[3])
        : "r"(a[0]), "r"(a[1]), "r"(a[2]), "r"(a[3]), "r"(b[0]), "r"(b[1]));
}

// acc[8][4] += Xtile[128 x 8*KSTEPS] @ Wtile[64 x 8*KSTEPS]^T via ldmatrix frags.
template<int STRIDE, int KSTEPS>
__device__ __forceinline__ void mma_tile(uint32_t xs, uint32_t ws, float acc[8][4]) {
    const int lane = threadIdx.x & 31;
    const int warp = threadIdx.x >> 5;
    const uint32_t a_addr = xs +
        ((uint32_t)((warp * 16 + (lane & 7) + ((lane >> 3) & 1) * 8) * STRIDE
                    + ((lane >> 4) & 1) * 4)) * 4u;
    const uint32_t b_addr = ws +
        ((uint32_t)(((lane & 7) + ((lane >> 4) & 1) * 8) * STRIDE
                    + ((lane >> 3) & 1) * 4)) * 4u;
#pragma unroll
    for (int ks = 0; ks < KSTEPS; ks++) {
        uint32_t a[4];
        ldsm_x4(a, a_addr + ks * 32);
#pragma unroll
        for (int p = 0; p < 4; p++) {
            uint32_t b[4];
            ldsm_x4(b, b_addr + (uint32_t)(p * 16 * STRIDE * 4) + ks * 32);
            mma8(acc[2 * p],     a, b);
            mma8(acc[2 * p + 1], a, b + 2);
        }
    }
}

// Per-thread register staging fragment: X chunk [128x32] + W chunk [64x32]
struct Frag {
    float4 x[4];
    float4 w[2];
};

__device__ __forceinline__ Frag ldg_chunk(const float* __restrict__ X,
                                          const float* __restrict__ W,
                                          int baseRow, int kc) {
    Frag f;
    const int tid = threadIdx.x;
    const int r  = tid >> 3;         // 0..31
    const int c4 = (tid & 7) * 4;    // 0,4,...,28
#pragma unroll
    for (int rr = 0; rr < 4; rr++)
        f.x[rr] = *(const float4*)(X + (size_t)(baseRow + r + rr * 32) * D_MODEL + kc + c4);
#pragma unroll
    for (int rr = 0; rr < 2; rr++)
        f.w[rr] = *(const float4*)(W + (size_t)(r + rr * 32) * D_MODEL + kc + c4);
    return f;
}

__device__ __forceinline__ void sts_chunk(const Frag& f, uint32_t* Xs, uint32_t* Ws) {
    const int tid = threadIdx.x;
    const int r  = tid >> 3;
    const int c4 = (tid & 7) * 4;
#pragma unroll
    for (int rr = 0; rr < 4; rr++) {
        uint4 o; o.x = f2tf(f.x[rr].x); o.y = f2tf(f.x[rr].y); o.z = f2tf(f.x[rr].z); o.w = f2tf(f.x[rr].w);
        *(uint4*)(Xs + (r + rr * 32) * XSTRIDE + c4) = o;
    }
#pragma unroll
    for (int rr = 0; rr < 2; rr++) {
        uint4 o; o.x = f2tf(f.w[rr].x); o.y = f2tf(f.w[rr].y); o.z = f2tf(f.w[rr].z); o.w = f2tf(f.w[rr].w);
        *(uint4*)(Ws + (r + rr * 32) * XSTRIDE + c4) = o;
    }
}

// ---------------- Kernel 1: fused k&v projections + softmax-pool partials ----------------
// Pipelined: chunk c (c even -> value, odd -> key), kc = (c>>1)*KC. 1 barrier per chunk.
// No max-subtraction: k = key.Wk + bk has |k| << 80, exp cannot overflow.
__global__ void __launch_bounds__(256) kv_fused_kernel(
    const float* __restrict__ key_in, const float* __restrict__ value_in,
    const float* __restrict__ Wk, const float* __restrict__ bk,
    const float* __restrict__ Wv, const float* __restrict__ bv) {
    extern __shared__ uint32_t smem[];
    uint32_t* buf[2] = { smem, smem + STAGE_W };          // each: [X | W]
    float* pt = (float*)(smem + 2 * STAGE_W);             // [8][HIDDEN*2]

    const int tid  = threadIdx.x;
    const int lane = tid & 31;
    const int warp = tid >> 5;
    const int gid  = lane >> 2;
    const int ctid = lane & 3;
    const int baseRow = blockIdx.x * ROWS;

    const uint32_t xs0 = smem_u32(buf[0]), ws0 = xs0 + XBUF_W * 4;
    const uint32_t xs1 = smem_u32(buf[1]), ws1 = xs1 + XBUF_W * 4;

    float accv[8][4] = {};
    float acck[8][4] = {};

    const int NCH = 2 * (D_MODEL / KC);   // 64

    // prologue: chunk 0 (value, kc0) staged; chunk 1 (key, kc0) in regs
    Frag f = ldg_chunk(value_in, Wv, baseRow, 0);
    sts_chunk(f, buf[0], buf[0] + XBUF_W);
    f = ldg_chunk(key_in, Wk, baseRow, 0);

#pragma unroll 2
    for (int c = 0; c < NCH; c++) {
        __syncthreads();    // chunk c visible; all warps done with mma(c-1) -> buf[(c+1)&1] free
        if (c + 1 < NCH)
            sts_chunk(f, buf[(c + 1) & 1], buf[(c + 1) & 1] + XBUF_W);
        if (c + 2 < NCH) {
            const int m = (c + 2) & 1;
            f = ldg_chunk(m ? key_in : value_in, m ? Wk : Wv, baseRow, ((c + 2) >> 1) * KC);
        }
        if (c & 1) mma_tile<XSTRIDE, KC / 8>((c & 1) ? xs1 : xs0, (c & 1) ? ws1 : ws0, acck);
        else       mma_tile<XSTRIDE, KC / 8>((c & 1) ? xs1 : xs0, (c & 1) ? ws1 : ws0, accv);
    }

    // partials: se[col] = sum_rows exp(k), swv[col] = sum_rows exp(k)*v
#pragma unroll
    for (int nt = 0; nt < 8; nt++) {
        const int col = nt * 8 + 2 * ctid;
        const float bk0 = bk[col], bk1 = bk[col + 1];
        const float bv0 = bv[col], bv1 = bv[col + 1];
        const float e0 = __expf(acck[nt][0] + bk0);
        const float e1 = __expf(acck[nt][1] + bk1);
        const float e2 = __expf(acck[nt][2] + bk0);
        const float e3 = __expf(acck[nt][3] + bk1);
        float se0 = e0 + e2;
        float se1 = e1 + e3;
        float sw0 = e0 * (accv[nt][0] + bv0) + e2 * (accv[nt][2] + bv0);
        float sw1 = e1 * (accv[nt][1] + bv1) + e3 * (accv[nt][3] + bv1);
#pragma unroll
        for (int s = 16; s >= 4; s >>= 1) {
            se0 += __shfl_xor_sync(0xffffffffu, se0, s);
            se1 += __shfl_xor_sync(0xffffffffu, se1, s);
            sw0 += __shfl_xor_sync(0xffffffffu, sw0, s);
            sw1 += __shfl_xor_sync(0xffffffffu, sw1, s);
        }
        if (gid == 0) {
            pt[warp * HIDDEN * 2 + 2 * col]           = se0;
            pt[warp * HIDDEN * 2 + 2 * col + 1]       = sw0;
            pt[warp * HIDDEN * 2 + 2 * (col + 1)]     = se1;
            pt[warp * HIDDEN * 2 + 2 * (col + 1) + 1] = sw1;
        }
    }
    __syncthreads();
    if (tid < HIDDEN) {
        float se = 0.f, sw = 0.f;
#pragma unroll
        for (int w = 0; w < 8; w++) {
            se += pt[w * HIDDEN * 2 + 2 * tid];
            sw += pt[w * HIDDEN * 2 + 2 * tid + 1];
        }
        g_part[(blockIdx.x * HIDDEN + tid) * 2]     = se;
        g_part[(blockIdx.x * HIDDEN + tid) * 2 + 1] = sw;
    }
}

// ---------------- Kernel 2: combine per-block partials -> g_w ----------------
__global__ void __launch_bounds__(512) reduce2_kernel() {
    const int tid = threadIdx.x;         // 512 = 8 batches x 64 cols
    const int b = tid >> 6, h = tid & 63;
    float se = 0.f, sw = 0.f;
#pragma unroll 4
    for (int i = 0; i < 32; i++) {
        const int blk = b * 32 + i;      // 32 row-blocks per batch
        se += g_part[(blk * HIDDEN + h) * 2];
        sw += g_part[(blk * HIDDEN + h) * 2 + 1];
    }
    g_w[tid] = sw / se;
}

// ---------------- Kernel 3: fused q-proj -> sigmoid*weights -> Wp proj ----------------
__global__ void __launch_bounds__(256) out_kernel(
    const float* __restrict__ query, const float* __restrict__ Wq,
    const float* __restrict__ bq, const float* __restrict__ Wp,
    const float* __restrict__ bp, float* __restrict__ out) {
    extern __shared__ uint32_t smem[];
    uint32_t* buf[2] = { smem, smem + STAGE_W };           // stage 1
    uint32_t* Ys  = smem;                                  // stage 2, aliases stage-1 bufs
    uint32_t* Ps0 = smem + ROWS * YSTRIDE;                 // [64*68]
    uint32_t* Ps1 = Ps0 + HIDDEN * YSTRIDE;

    const int tid  = threadIdx.x;
    const int warp = tid >> 5;
    const int lane = tid & 31;
    const int gid  = lane >> 2;
    const int ctid = lane & 3;
    const int baseRow = blockIdx.x * ROWS;
    const int bidx = baseRow >> 12;        // 4096 rows per batch

    const uint32_t xs0 = smem_u32(buf[0]), ws0 = xs0 + XBUF_W * 4;
    const uint32_t xs1 = smem_u32(buf[1]), ws1 = xs1 + XBUF_W * 4;

    // ---- stage 1: q = query @ Wq^T, pipelined ----
    float acc[8][4] = {};
    const int NCH = D_MODEL / KC;   // 32
    Frag f = ldg_chunk(query, Wq, baseRow, 0);
    sts_chunk(f, buf[0], buf[0] + XBUF_W);
    f = ldg_chunk(query, Wq, baseRow, KC);

    for (int c = 0; c < NCH; c++) {
        __syncthreads();
        if (c + 1 < NCH)
            sts_chunk(f, buf[(c + 1) & 1], buf[(c + 1) & 1] + XBUF_W);
        if (c + 2 < NCH)
            f = ldg_chunk(query, Wq, baseRow, (c + 2) * KC);
        mma_tile<XSTRIDE, KC / 8>((c & 1) ? xs1 : xs0, (c & 1) ? ws1 : ws0, acc);
    }
    __syncthreads();   // all mma done before Ys overwrites buf region

    // epilogue: sigmoid(q + bq) * weights -> Ys (tf32)
#pragma unroll
    for (int nt = 0; nt < 8; nt++) {
        const int col = nt * 8 + 2 * ctid;
        const float b0 = bq[col], b1 = bq[col + 1];
        const float w0 = g_w[bidx * HIDDEN + col], w1 = g_w[bidx * HIDDEN + col + 1];
        const int r = warp * 16 + gid;
        const float q0 = acc[nt][0] + b0, q1 = acc[nt][1] + b1;
        const float q2 = acc[nt][2] + b0, q3 = acc[nt][3] + b1;
        Ys[r * YSTRIDE + col]           = f2tf(w0 / (1.f + __expf(-q0)));
        Ys[r * YSTRIDE + col + 1]       = f2tf(w1 / (1.f + __expf(-q1)));
        Ys[(r + 8) * YSTRIDE + col]     = f2tf(w0 / (1.f + __expf(-q2)));
        Ys[(r + 8) * YSTRIDE + col + 1] = f2tf(w1 / (1.f + __expf(-q3)));
    }

    const uint32_t ys_u = smem_u32(Ys);
    const uint32_t ps_u[2] = { smem_u32(Ps0), smem_u32(Ps1) };
    uint32_t* PsPtr[2] = { Ps0, Ps1 };

    // ---- stage 2: out = Ys @ Wp^T + bp, 16 chunks of 64 cols, double-buffered Ps ----
    // Per-thread Wp fragment: row = tid>>2, k-segs (tid&3)*4 + {0,16,32,48}
    const int pr  = tid >> 2;
    const int pc4 = (tid & 3) * 4;
    float4 pf[4];
#pragma unroll
    for (int cc = 0; cc < 4; cc++)
        pf[cc] = *(const float4*)(Wp + (size_t)pr * HIDDEN + cc * 16 + pc4);
    {
        // store chunk 0 now; prefetch chunk 1
#pragma unroll
        for (int cc = 0; cc < 4; cc++) {
            uint4 o; o.x = f2tf(pf[cc].x); o.y = f2tf(pf[cc].y); o.z = f2tf(pf[cc].z); o.w = f2tf(pf[cc].w);
            *(uint4*)(Ps0 + pr * YSTRIDE + cc * 16 + pc4) = o;
        }
#pragma unroll
        for (int cc = 0; cc < 4; cc++)
            pf[cc] = *(const float4*)(Wp + (size_t)(64 + pr) * HIDDEN + cc * 16 + pc4);
    }

    for (int ncI = 0; ncI < 16; ncI++) {
        __syncthreads();   // Ps[ncI&1] (and Ys on iter 0) visible; prior mma consumers done
        if (ncI + 1 < 16) {
            uint32_t* Pd = PsPtr[(ncI + 1) & 1];
#pragma unroll
            for (int cc = 0; cc < 4; cc++) {
                uint4 o; o.x = f2tf(pf[cc].x); o.y = f2tf(pf[cc].y); o.z = f2tf(pf[cc].z); o.w = f2tf(pf[cc].w);
                *(uint4*)(Pd + pr * YSTRIDE + cc * 16 + pc4) = o;
            }
        }
        if (ncI + 2 < 16) {
#pragma unroll
            for (int cc = 0; cc < 4; cc++)
                pf[cc] = *(const float4*)(Wp + (size_t)((ncI + 2) * 64 + pr) * HIDDEN + cc * 16 + pc4);
        }

        float oacc[8][4] = {};
        mma_tile<YSTRIDE, HIDDEN / 8>(ys_u, ps_u[ncI & 1], oacc);

        const int nc = ncI * 64;
#pragma unroll
        for (int nt = 0; nt < 8; nt++) {
            const int col = nc + nt * 8 + 2 * ctid;
            const float b0 = bp[col], b1 = bp[col + 1];
            const size_t r0 = (size_t)(baseRow + warp * 16 + gid);
            *(float2*)(out + r0 * D_MODEL + col) = make_float2(oacc[nt][0] + b0, oacc[nt][1] + b1);
            *(float2*)(out + (r0 + 8) * D_MODEL + col) = make_float2(oacc[nt][2] + b0, oacc[nt][3] + b1);
        }
    }
}

extern "C" void kernel_launch(void* const* d_in, const int* in_sizes, int n_in,
                              void* d_out, int out_size) {
    const float* query = (const float*)d_in[0];
    const float* key_in = (const float*)d_in[1];
    const float* value_in = (const float*)d_in[2];
    const float* Wq = (const float*)d_in[3];
    const float* bq = (const float*)d_in[4];
    const float* Wk = (const float*)d_in[5];
    const float* bk = (const float*)d_in[6];
    const float* Wv = (const float*)d_in[7];
    const float* bv = (const float*)d_in[8];
    const float* Wp = (const float*)d_in[9];
    const float* bp = (const float*)d_in[10];
    float* out = (float*)d_out;

    const int smem_kv  = 2 * STAGE_W * 4 + 8 * HIDDEN * 2 * 4;                 // 59392 B
    const int smem_out = (ROWS * YSTRIDE + 2 * HIDDEN * YSTRIDE) * 4;          // 69632 B
    cudaFuncSetAttribute(kv_fused_kernel, cudaFuncAttributeMaxDynamicSharedMemorySize, smem_kv);
    cudaFuncSetAttribute(out_kernel, cudaFuncAttributeMaxDynamicSharedMemorySize, smem_out);

    kv_fused_kernel<<<256, 256, smem_kv>>>(key_in, value_in, Wk, bk, Wv, bv);
    reduce2_kernel<<<1, 512>>>();
    out_kernel<<<256, 256, smem_out>>>(query, Wq, bq, Wp, bp, out);
}